// round 6
// baseline (speedup 1.0000x reference)
#include <cuda_runtime.h>
#include <math.h>

#define NTOK   16384
#define DIM    128
#define NGRAPH 128
#define NBLK   10
#define LCAP   208    // max supported segment length (mu=128, sigma~11.3 -> +7.1 sigma)

// ---------------- scratch (no allocations allowed) ----------------
__device__ float g_x[NTOK * DIM];          // residual stream
__device__ float g_y[NTOK * DIM];          // attention output
__device__ float g_qkv[NTOK * 3 * DIM];
__device__ float g_h1[NTOK * 4 * DIM];
__device__ float g_mu[NTOK];               // per-token LN mean of current x
__device__ float g_rsd[NTOK];              // per-token LN rstd of current x
__device__ int   g_off[NGRAPH + 1];
__device__ float g_bnmu[16];
__device__ float g_bnrs[16];

__device__ __forceinline__ float fast_tanh(float v) {
    float r;
    asm("tanh.approx.f32 %0, %1;" : "=f"(r) : "f"(v));
    return r;
}

// ---------------- segment offsets (batch_idx is sorted) ----------------
__global__ void offsets_kernel(const int* __restrict__ bidx) {
    int g = threadIdx.x;
    if (g <= NGRAPH) {
        int lo = 0, hi = NTOK;
        while (lo < hi) { int mid = (lo + hi) >> 1; if (bidx[mid] < g) lo = mid + 1; else hi = mid; }
        g_off[g] = lo;
    }
}

// ---------------- BatchNorm statistics (training-mode, biased var) ----------------
__global__ void bn_stats(const float* __restrict__ s13, const float* __restrict__ v3) {
    int c = blockIdx.x;          // channel 0..15
    int tid = threadIdx.x;
    float sum = 0.f, sq = 0.f;
    for (int n = tid; n < NTOK; n += 256) {
        float v = (c < 13) ? s13[n * 13 + c] : v3[n * 3 + (c - 13)];
        sum += v; sq += v * v;
    }
    __shared__ float ssum[256], ssq[256];
    ssum[tid] = sum; ssq[tid] = sq;
    __syncthreads();
    for (int st = 128; st; st >>= 1) {
        if (tid < st) { ssum[tid] += ssum[tid + st]; ssq[tid] += ssq[tid + st]; }
        __syncthreads();
    }
    if (tid == 0) {
        float mu = ssum[0] / (float)NTOK;
        float var = ssq[0] / (float)NTOK - mu * mu;
        g_bnmu[c] = mu;
        g_bnrs[c] = rsqrtf(var + 1e-5f);
    }
}

// ---------------- BN-normalize + input projection 16 -> 128 (+ LN stats) ----------------
__global__ void input_proj(const float* __restrict__ s13, const float* __restrict__ v3,
                           const float* __restrict__ gamma, const float* __restrict__ beta,
                           const float* __restrict__ w_in, const float* __restrict__ b_in,
                           float* __restrict__ x) {
    __shared__ float xn[16];
    __shared__ float ws[8];
    int t = blockIdx.x;
    int tid = threadIdx.x;      // 128 threads
    if (tid < 16) {
        float raw = (tid < 13) ? s13[t * 13 + tid] : v3[t * 3 + (tid - 13)];
        xn[tid] = (raw - g_bnmu[tid]) * g_bnrs[tid] * gamma[tid] + beta[tid];
    }
    __syncthreads();
    float acc = b_in[tid];
#pragma unroll
    for (int k = 0; k < 16; k++) acc += xn[k] * w_in[k * 128 + tid];
    x[t * 128 + tid] = acc;

    // LN stats for block-0 ln1
    float s1 = acc, s2 = acc * acc;
    for (int off = 16; off; off >>= 1) {
        s1 += __shfl_xor_sync(0xffffffffu, s1, off);
        s2 += __shfl_xor_sync(0xffffffffu, s2, off);
    }
    int warp = tid >> 5, lane = tid & 31;
    if (lane == 0) { ws[warp] = s1; ws[4 + warp] = s2; }
    __syncthreads();
    if (tid == 0) {
        float sum = ws[0] + ws[1] + ws[2] + ws[3];
        float sq  = ws[4] + ws[5] + ws[6] + ws[7];
        float mean = sum * (1.f / 128.f);
        float var  = sq * (1.f / 128.f) - mean * mean;
        g_mu[t]  = mean;
        g_rsd[t] = rsqrtf(var + 1e-5f);
    }
}

// ---------------- SGEMM 128x128x8, 8x8 microtile, double-buffered ----------------
// ACT: 0 none, 1 gelu(tanh). RES: 0 store, 1 C = Cres + result.
// LNA: 1 => A normalized on the fly: (a - mu[row]) * rsd[row] * lng[col] + lnb[col]
// STATS: 1 => epilogue writes per-row LN stats of C (requires Nc==128, gridDim.y==1)
template <int ACT, int RES, int LNA, int STATS>
__global__ void __launch_bounds__(256) gemm128(const float* __restrict__ A,
                                               const float* __restrict__ B,
                                               const float* __restrict__ bias,
                                               const float* Cres, float* C,
                                               int K, int Nc,
                                               const float* __restrict__ lng,
                                               const float* __restrict__ lnb) {
    __shared__ float As[2][8][128];
    __shared__ float Bs[2][8][128];
    int tid = threadIdx.x;
    int m0 = blockIdx.x * 128, n0 = blockIdx.y * 128;
    int ty = tid >> 4, tx = tid & 15;
    float acc[8][8];
#pragma unroll
    for (int i = 0; i < 8; i++)
#pragma unroll
        for (int j = 0; j < 8; j++) acc[i][j] = 0.f;

    int am = tid >> 1;           // 0..127 (A row within tile)
    int aq = (tid & 1) * 4;      // k sub-offset 0 / 4
    int bk = tid >> 5;           // 0..7   (B row within tile)
    int bn = (tid & 31) * 4;     // col within tile
    const float* Ap = A + (size_t)(m0 + am) * K + aq;
    const float* Bp = B + (size_t)bk * Nc + n0 + bn;

    float rowmu = 0.f, rowrs = 1.f;
    if (LNA) { rowmu = g_mu[m0 + am]; rowrs = g_rsd[m0 + am]; }

    // prologue: load k0 = 0
    float4 a4 = *(const float4*)(Ap);
    float4 b4 = *(const float4*)(Bp);
    if (LNA) {
        float4 g4 = *(const float4*)(lng + aq);
        float4 q4 = *(const float4*)(lnb + aq);
        a4.x = (a4.x - rowmu) * rowrs * g4.x + q4.x;
        a4.y = (a4.y - rowmu) * rowrs * g4.y + q4.y;
        a4.z = (a4.z - rowmu) * rowrs * g4.z + q4.z;
        a4.w = (a4.w - rowmu) * rowrs * g4.w + q4.w;
    }
    int buf = 0;
    As[0][aq + 0][am] = a4.x; As[0][aq + 1][am] = a4.y;
    As[0][aq + 2][am] = a4.z; As[0][aq + 3][am] = a4.w;
    *(float4*)&Bs[0][bk][bn] = b4;
    __syncthreads();

    for (int k0 = 8; k0 < K; k0 += 8) {
        float4 an = *(const float4*)(Ap + k0);
        float4 bnv = *(const float4*)(Bp + (size_t)k0 * Nc);
        if (LNA) {
            float4 g4 = *(const float4*)(lng + k0 + aq);
            float4 q4 = *(const float4*)(lnb + k0 + aq);
            an.x = (an.x - rowmu) * rowrs * g4.x + q4.x;
            an.y = (an.y - rowmu) * rowrs * g4.y + q4.y;
            an.z = (an.z - rowmu) * rowrs * g4.z + q4.z;
            an.w = (an.w - rowmu) * rowrs * g4.w + q4.w;
        }
#pragma unroll
        for (int k = 0; k < 8; k++) {
            float ra[8], rb[8];
            *(float4*)(ra)     = *(const float4*)&As[buf][k][ty * 8];
            *(float4*)(ra + 4) = *(const float4*)&As[buf][k][ty * 8 + 4];
            *(float4*)(rb)     = *(const float4*)&Bs[buf][k][tx * 8];
            *(float4*)(rb + 4) = *(const float4*)&Bs[buf][k][tx * 8 + 4];
#pragma unroll
            for (int i = 0; i < 8; i++)
#pragma unroll
                for (int j = 0; j < 8; j++) acc[i][j] += ra[i] * rb[j];
        }
        buf ^= 1;
        As[buf][aq + 0][am] = an.x; As[buf][aq + 1][am] = an.y;
        As[buf][aq + 2][am] = an.z; As[buf][aq + 3][am] = an.w;
        *(float4*)&Bs[buf][bk][bn] = bnv;
        __syncthreads();
    }

#pragma unroll
    for (int k = 0; k < 8; k++) {
        float ra[8], rb[8];
        *(float4*)(ra)     = *(const float4*)&As[buf][k][ty * 8];
        *(float4*)(ra + 4) = *(const float4*)&As[buf][k][ty * 8 + 4];
        *(float4*)(rb)     = *(const float4*)&Bs[buf][k][tx * 8];
        *(float4*)(rb + 4) = *(const float4*)&Bs[buf][k][tx * 8 + 4];
#pragma unroll
        for (int i = 0; i < 8; i++)
#pragma unroll
            for (int j = 0; j < 8; j++) acc[i][j] += ra[i] * rb[j];
    }

#pragma unroll
    for (int i = 0; i < 8; i++) {
        int row = m0 + ty * 8 + i;
        float* Cp = C + (size_t)row * Nc + n0 + tx * 8;
        const float* Rp = Cres + (size_t)row * Nc + n0 + tx * 8;   // only read when RES==1
        float s1 = 0.f, s2 = 0.f;
#pragma unroll
        for (int j = 0; j < 8; j++) {
            float v = acc[i][j] + bias[n0 + tx * 8 + j];
            if (ACT == 1) {
                float u = v;
                v = 0.5f * u * (1.f + fast_tanh(0.7978845608028654f * (u + 0.044715f * u * u * u)));
            }
            if (RES == 1) v += Rp[j];
            Cp[j] = v;
            if (STATS) { s1 += v; s2 += v * v; }
        }
        if (STATS) {
            // full row lives across the 16 tx lanes of this ty half-warp
#pragma unroll
            for (int off = 1; off < 16; off <<= 1) {
                s1 += __shfl_xor_sync(0xffffffffu, s1, off);
                s2 += __shfl_xor_sync(0xffffffffu, s2, off);
            }
            if (tx == 0) {
                float mean = s1 * (1.f / 128.f);
                float var  = s2 * (1.f / 128.f) - mean * mean;
                g_mu[row]  = mean;
                g_rsd[row] = rsqrtf(var + 1e-5f);
            }
        }
    }
}

// ---------------- ragged attention: one CTA per (graph, head), 12 warps ----------------
// smem: Ks[LCAP][33], Vs[LCAP][33] (pad-33 => conflict-free),
//       Pr4[12 warps][LCAP] float4 (probs for 4 queries, key-major).
// Total ~92.6 KB -> 2 CTAs/SM; 384 threads => 85-reg budget (no spills).
#define ATTN_WARPS 12
#define ATTN_SMEM ((2 * LCAP * 33) * (int)sizeof(float) + ATTN_WARPS * LCAP * (int)sizeof(float4))

__global__ void __launch_bounds__(32 * ATTN_WARPS, 2) attn_kernel(const float* __restrict__ qkv,
                                                                  float* __restrict__ yout) {
    extern __shared__ float sm[];
    float*  Ks  = sm;
    float*  Vs  = sm + LCAP * 33;
    float4* Pr4 = (float4*)(sm + 2 * LCAP * 33);
    int g = blockIdx.x, h = blockIdx.y;
    int base = g_off[g];
    int L = g_off[g + 1] - base;
    if (L <= 0) return;
    if (L > LCAP) L = LCAP;   // statistically unreachable (mu+7.1sigma); guards smem
    int tid = threadIdx.x;

    // load K,V (zero-fill pads up to the next multiple of 128 keys, capped at LCAP)
    int Lpad = (L + 127) & ~127;
    if (Lpad > LCAP) Lpad = LCAP;
    for (int idx = tid; idx < Lpad * 32; idx += 32 * ATTN_WARPS) {
        int m = idx >> 5, d = idx & 31;
        float kv = 0.f, vv = 0.f;
        if (m < L) {
            const float* p = qkv + (size_t)(base + m) * 384 + h * 32 + d;
            kv = p[128];
            vv = p[256];
        }
        Ks[m * 33 + d] = kv;
        Vs[m * 33 + d] = vv;
    }
    __syncthreads();

    int warp = tid >> 5, lane = tid & 31;
    float4* prw = Pr4 + warp * LCAP;
    const float scale = 0.17677669529663687f;   // 1/sqrt(32)
    int ngrp = (L + 3) >> 2;
    int njt = (L + 31) >> 5;                    // number of 32-key tiles (<=7)

    for (int grp = warp; grp < ngrp; grp += ATTN_WARPS) {
        int q0 = grp * 4;
        float qreg[4];
#pragma unroll
        for (int qi = 0; qi < 4; qi++) {
            int q = q0 + qi;
            qreg[qi] = (q < L) ? qkv[(size_t)(base + q) * 384 + h * 32 + lane] : 0.f;
        }
        float s[4][7];
#pragma unroll
        for (int qi = 0; qi < 4; qi++)
#pragma unroll
            for (int j = 0; j < 7; j++) s[qi][j] = 0.f;

        // scores: lane owns keys lane + 32j, j < njt
        for (int d = 0; d < 32; d++) {
            float kd[7];
#pragma unroll
            for (int j = 0; j < 7; j++) kd[j] = (j < njt) ? Ks[(lane + 32 * j) * 33 + d] : 0.f;
#pragma unroll
            for (int qi = 0; qi < 4; qi++) {
                float qd = __shfl_sync(0xffffffffu, qreg[qi], d);
#pragma unroll
                for (int j = 0; j < 7; j++) s[qi][j] += qd * kd[j];
            }
        }

        // softmax per query (normalize s in place; invalid keys overwritten by mask)
#pragma unroll
        for (int qi = 0; qi < 4; qi++) {
            float mx = -3e38f;
#pragma unroll
            for (int j = 0; j < 7; j++) {
                int m = lane + 32 * j;
                s[qi][j] = (m < L) ? s[qi][j] * scale : -3e38f;
                mx = fmaxf(mx, s[qi][j]);
            }
            for (int off = 16; off; off >>= 1) mx = fmaxf(mx, __shfl_xor_sync(0xffffffffu, mx, off));
            float sum = 0.f;
#pragma unroll
            for (int j = 0; j < 7; j++) { float e = __expf(s[qi][j] - mx); s[qi][j] = e; sum += e; }
            for (int off = 16; off; off >>= 1) sum += __shfl_xor_sync(0xffffffffu, sum, off);
            float inv = 1.f / sum;
#pragma unroll
            for (int j = 0; j < 7; j++) s[qi][j] *= inv;
        }
        // write probabilities key-major as float4 (q0..q3)
#pragma unroll
        for (int j = 0; j < 7; j++) {
            if (j < njt) {
                float4 p; p.x = s[0][j]; p.y = s[1][j]; p.z = s[2][j]; p.w = s[3][j];
                prw[lane + 32 * j] = p;
            }
        }
        __syncwarp();

        // A @ V: lane owns output dim `lane`; prw[m] is a warp-broadcast float4
        float o[4] = {0.f, 0.f, 0.f, 0.f};
        for (int m = 0; m < L; m++) {
            float4 p = prw[m];
            float v = Vs[m * 33 + lane];
            o[0] += p.x * v; o[1] += p.y * v; o[2] += p.z * v; o[3] += p.w * v;
        }
#pragma unroll
        for (int qi = 0; qi < 4; qi++) {
            int q = q0 + qi;
            if (q < L) yout[(size_t)(base + q) * 128 + h * 32 + lane] = o[qi];
        }
        __syncwarp();
    }
}

// ---------------- final LN (stats precomputed) + 128 -> 4 proj + sigmoid ----------------
__global__ void out_proj(const float* __restrict__ x,
                         const float* __restrict__ lng, const float* __restrict__ lnb,
                         const float* __restrict__ w,
                         const float* __restrict__ b, float* __restrict__ out) {
    int t = blockIdx.x * 8 + (threadIdx.x >> 5);
    int lane = threadIdx.x & 31;
    float4 v = ((const float4*)(x + (size_t)t * 128))[lane];
    float mean = g_mu[t];
    float rs   = g_rsd[t];
    float4 g4 = ((const float4*)lng)[lane];
    float4 b4 = ((const float4*)lnb)[lane];
    float vv[4];
    vv[0] = (v.x - mean) * rs * g4.x + b4.x;
    vv[1] = (v.y - mean) * rs * g4.y + b4.y;
    vv[2] = (v.z - mean) * rs * g4.z + b4.z;
    vv[3] = (v.w - mean) * rs * g4.w + b4.w;

    float a[4] = {0.f, 0.f, 0.f, 0.f};
    const float* wr = w + lane * 16;        // rows lane*4 .. lane*4+3, 4 cols each
#pragma unroll
    for (int r = 0; r < 4; r++)
#pragma unroll
        for (int o = 0; o < 4; o++) a[o] += vv[r] * wr[r * 4 + o];
    for (int off = 16; off; off >>= 1)
#pragma unroll
        for (int o = 0; o < 4; o++) a[o] += __shfl_xor_sync(0xffffffffu, a[o], off);
    if (lane == 0) {
        out[t * 4 + 0] = a[0] + b[0];
        out[t * 4 + 1] = a[1] + b[1];
        out[t * 4 + 2] = a[2] + b[2];
        float z = a[3] + b[3];
        out[t * 4 + 3] = 1.f / (1.f + expf(-z));
    }
}

// ---------------- launch ----------------
extern "C" void kernel_launch(void* const* d_in, const int* in_sizes, int n_in,
                              void* d_out, int out_size) {
    (void)in_sizes; (void)n_in; (void)out_size;
    const float* s13  = (const float*)d_in[0];
    const float* v3   = (const float*)d_in[1];
    const int*   bidx = (const int*)d_in[2];
    const float* bn_g = (const float*)d_in[3];
    const float* bn_b = (const float*)d_in[4];
    const float* w_in = (const float*)d_in[5];
    const float* b_in = (const float*)d_in[6];
    const float* ln1g = (const float*)d_in[7];
    const float* ln1b = (const float*)d_in[8];
    const float* wqkv = (const float*)d_in[9];
    const float* bqkv = (const float*)d_in[10];
    const float* wo   = (const float*)d_in[11];
    const float* bo   = (const float*)d_in[12];
    const float* ln2g = (const float*)d_in[13];
    const float* ln2b = (const float*)d_in[14];
    const float* wm1  = (const float*)d_in[15];
    const float* bm1  = (const float*)d_in[16];
    const float* wm2  = (const float*)d_in[17];
    const float* bm2  = (const float*)d_in[18];
    const float* lnfg = (const float*)d_in[19];
    const float* lnfb = (const float*)d_in[20];
    const float* wout = (const float*)d_in[21];
    const float* bout = (const float*)d_in[22];

    float *x, *y, *qkv, *h1;
    cudaGetSymbolAddress((void**)&x,   g_x);
    cudaGetSymbolAddress((void**)&y,   g_y);
    cudaGetSymbolAddress((void**)&qkv, g_qkv);
    cudaGetSymbolAddress((void**)&h1,  g_h1);

    cudaFuncSetAttribute(attn_kernel, cudaFuncAttributeMaxDynamicSharedMemorySize, ATTN_SMEM);

    offsets_kernel<<<1, 192>>>(bidx);
    bn_stats<<<16, 256>>>(s13, v3);
    input_proj<<<NTOK, 128>>>(s13, v3, bn_g, bn_b, w_in, b_in, x);   // writes x + ln1 stats

    for (int i = 0; i < NBLK; i++) {
        // qkv = LN1(x) @ wqkv + b   (LN applied on the fly from g_mu/g_rsd)
        gemm128<0, 0, 1, 0><<<dim3(128, 3), 256>>>(x, wqkv + (size_t)i * 128 * 384, bqkv + i * 384,
                                                   x, qkv, 128, 384, ln1g + i * 128, ln1b + i * 128);
        attn_kernel<<<dim3(NGRAPH, 4), 32 * ATTN_WARPS, ATTN_SMEM>>>(qkv, y);
        // x += y @ wo + b ; epilogue writes LN2 stats of new x
        gemm128<0, 1, 0, 1><<<dim3(128, 1), 256>>>(y, wo + (size_t)i * 128 * 128, bo + i * 128,
                                                   x, x, 128, 128, ln1g, ln1b);
        // h1 = gelu(LN2(x) @ wm1 + b)
        gemm128<1, 0, 1, 0><<<dim3(128, 4), 256>>>(x, wm1 + (size_t)i * 128 * 512, bm1 + i * 512,
                                                   x, h1, 128, 512, ln2g + i * 128, ln2b + i * 128);
        // x += h1 @ wm2 + b ; epilogue writes stats for next ln1 (or final LN)
        gemm128<0, 1, 0, 1><<<dim3(128, 1), 256>>>(h1, wm2 + (size_t)i * 512 * 128, bm2 + i * 128,
                                                   x, x, 512, 128, ln2g, ln2b);
    }

    out_proj<<<NTOK / 8, 256>>>(x, lnfg, lnfb, wout, bout, (float*)d_out);
}

// round 9
// speedup vs baseline: 1.5002x; 1.5002x over previous
#include <cuda_runtime.h>
#include <math.h>
#include <stdint.h>

#define NTOK   16384
#define DIM    128
#define NGRAPH 128
#define NBLK   10
#define LCAP   208    // max supported segment length (mu=128, sigma~11.3 -> +7.1 sigma)

// ---------------- scratch (no allocations allowed) ----------------
__device__ float g_x[NTOK * DIM];          // residual stream
__device__ float g_y[NTOK * DIM];          // attention output
__device__ float g_qkv[NTOK * 3 * DIM];
__device__ float g_h1[NTOK * 4 * DIM];
__device__ float g_mu[NTOK];               // per-token LN mean of current x
__device__ float g_rsd[NTOK];              // per-token LN rstd of current x
__device__ int   g_off[NGRAPH + 1];
__device__ float g_bnmu[16];
__device__ float g_bnrs[16];

__device__ __forceinline__ float fast_tanh(float v) {
    float r;
    asm("tanh.approx.f32 %0, %1;" : "=f"(r) : "f"(v));
    return r;
}
__device__ __forceinline__ uint32_t f2tf32(float v) {
    uint32_t r;
    asm("cvt.rna.tf32.f32 %0, %1;" : "=r"(r) : "f"(v));
    return r;
}
__device__ __forceinline__ void mma_tf32(float* d, uint32_t a0, uint32_t a1, uint32_t a2, uint32_t a3,
                                         uint32_t b0, uint32_t b1) {
    asm volatile("mma.sync.aligned.m16n8k8.row.col.f32.tf32.tf32.f32 "
                 "{%0,%1,%2,%3}, {%4,%5,%6,%7}, {%8,%9}, {%0,%1,%2,%3};"
                 : "+f"(d[0]), "+f"(d[1]), "+f"(d[2]), "+f"(d[3])
                 : "r"(a0), "r"(a1), "r"(a2), "r"(a3), "r"(b0), "r"(b1));
}

// ---------------- segment offsets (batch_idx is sorted) ----------------
__global__ void offsets_kernel(const int* __restrict__ bidx) {
    int g = threadIdx.x;
    if (g <= NGRAPH) {
        int lo = 0, hi = NTOK;
        while (lo < hi) { int mid = (lo + hi) >> 1; if (bidx[mid] < g) lo = mid + 1; else hi = mid; }
        g_off[g] = lo;
    }
}

// ---------------- BatchNorm statistics (training-mode, biased var) ----------------
__global__ void bn_stats(const float* __restrict__ s13, const float* __restrict__ v3) {
    int c = blockIdx.x;          // channel 0..15
    int tid = threadIdx.x;
    float sum = 0.f, sq = 0.f;
    for (int n = tid; n < NTOK; n += 256) {
        float v = (c < 13) ? s13[n * 13 + c] : v3[n * 3 + (c - 13)];
        sum += v; sq += v * v;
    }
    __shared__ float ssum[256], ssq[256];
    ssum[tid] = sum; ssq[tid] = sq;
    __syncthreads();
    for (int st = 128; st; st >>= 1) {
        if (tid < st) { ssum[tid] += ssum[tid + st]; ssq[tid] += ssq[tid + st]; }
        __syncthreads();
    }
    if (tid == 0) {
        float mu = ssum[0] / (float)NTOK;
        float var = ssq[0] / (float)NTOK - mu * mu;
        g_bnmu[c] = mu;
        g_bnrs[c] = rsqrtf(var + 1e-5f);
    }
}

// ---------------- BN-normalize + input projection 16 -> 128 (+ LN stats) ----------------
__global__ void input_proj(const float* __restrict__ s13, const float* __restrict__ v3,
                           const float* __restrict__ gamma, const float* __restrict__ beta,
                           const float* __restrict__ w_in, const float* __restrict__ b_in,
                           float* __restrict__ x) {
    __shared__ float xn[16];
    __shared__ float ws[8];
    int t = blockIdx.x;
    int tid = threadIdx.x;      // 128 threads
    if (tid < 16) {
        float raw = (tid < 13) ? s13[t * 13 + tid] : v3[t * 3 + (tid - 13)];
        xn[tid] = (raw - g_bnmu[tid]) * g_bnrs[tid] * gamma[tid] + beta[tid];
    }
    __syncthreads();
    float acc = b_in[tid];
#pragma unroll
    for (int k = 0; k < 16; k++) acc += xn[k] * w_in[k * 128 + tid];
    x[t * 128 + tid] = acc;

    // LN stats for block-0 ln1
    float s1 = acc, s2 = acc * acc;
    for (int off = 16; off; off >>= 1) {
        s1 += __shfl_xor_sync(0xffffffffu, s1, off);
        s2 += __shfl_xor_sync(0xffffffffu, s2, off);
    }
    int warp = tid >> 5, lane = tid & 31;
    if (lane == 0) { ws[warp] = s1; ws[4 + warp] = s2; }
    __syncthreads();
    if (tid == 0) {
        float sum = ws[0] + ws[1] + ws[2] + ws[3];
        float sq  = ws[4] + ws[5] + ws[6] + ws[7];
        float mean = sum * (1.f / 128.f);
        float var  = sq * (1.f / 128.f) - mean * mean;
        g_mu[t]  = mean;
        g_rsd[t] = rsqrtf(var + 1e-5f);
    }
}

// ---------------- TF32 tensor-core GEMM, CTA 128x128, 8 warps x (16 rows x 128 cols) ----------------
// smem stride 136 floats (136 % 32 == 8) => conflict-free fragment LDS.
// ACT: gelu. RES: +Cres. LNA: LN A rows on load. STATS: write per-row LN stats of C (Nc==128, grid.y==1).
#define SSTR 136
template <int ACT, int RES, int LNA, int STATS>
__global__ void __launch_bounds__(256) gemm_tc(const float* __restrict__ A,
                                               const float* __restrict__ B,
                                               const float* __restrict__ bias,
                                               const float* Cres, float* C,
                                               int K, int Nc,
                                               const float* __restrict__ lng,
                                               const float* __restrict__ lnb) {
    __shared__ float As[2][8][SSTR];
    __shared__ float Bs[2][8][SSTR];
    int tid = threadIdx.x;
    int m0 = blockIdx.x * 128, n0 = blockIdx.y * 128;
    int warp = tid >> 5, lane = tid & 31;
    int g = lane >> 2, t = lane & 3;

    float acc[16][4];
#pragma unroll
    for (int j = 0; j < 16; j++)
#pragma unroll
        for (int r = 0; r < 4; r++) acc[j][r] = 0.f;

    // staging indices
    int am = tid >> 1;            // A row within tile (0..127)
    int aq = (tid & 1) * 4;       // k sub-offset 0/4
    int bk = tid >> 5;            // B k-row (0..7)
    int bn = (tid & 31) * 4;      // B col within tile
    const float* Ap = A + (size_t)(m0 + am) * K + aq;
    const float* Bp = B + (size_t)bk * Nc + n0 + bn;

    float rowmu = 0.f, rowrs = 1.f;
    if (LNA) { rowmu = g_mu[m0 + am]; rowrs = g_rsd[m0 + am]; }

    // ---- stage k0 = 0 ----
    {
        float4 a4 = *(const float4*)(Ap);
        float4 b4 = *(const float4*)(Bp);
        if (LNA) {
            float4 g4 = *(const float4*)(lng + aq);
            float4 q4 = *(const float4*)(lnb + aq);
            a4.x = (a4.x - rowmu) * rowrs * g4.x + q4.x;
            a4.y = (a4.y - rowmu) * rowrs * g4.y + q4.y;
            a4.z = (a4.z - rowmu) * rowrs * g4.z + q4.z;
            a4.w = (a4.w - rowmu) * rowrs * g4.w + q4.w;
        }
        As[0][aq + 0][am] = __uint_as_float(f2tf32(a4.x));
        As[0][aq + 1][am] = __uint_as_float(f2tf32(a4.y));
        As[0][aq + 2][am] = __uint_as_float(f2tf32(a4.z));
        As[0][aq + 3][am] = __uint_as_float(f2tf32(a4.w));
        float4 bc;
        bc.x = __uint_as_float(f2tf32(b4.x));
        bc.y = __uint_as_float(f2tf32(b4.y));
        bc.z = __uint_as_float(f2tf32(b4.z));
        bc.w = __uint_as_float(f2tf32(b4.w));
        *(float4*)&Bs[0][bk][bn] = bc;
    }
    __syncthreads();

    int buf = 0;
    for (int k0 = 8; k0 < K; k0 += 8) {
        // prefetch next
        float4 a4 = *(const float4*)(Ap + k0);
        float4 b4 = *(const float4*)(Bp + (size_t)k0 * Nc);
        if (LNA) {
            float4 g4 = *(const float4*)(lng + k0 + aq);
            float4 q4 = *(const float4*)(lnb + k0 + aq);
            a4.x = (a4.x - rowmu) * rowrs * g4.x + q4.x;
            a4.y = (a4.y - rowmu) * rowrs * g4.y + q4.y;
            a4.z = (a4.z - rowmu) * rowrs * g4.z + q4.z;
            a4.w = (a4.w - rowmu) * rowrs * g4.w + q4.w;
        }
        // compute current buffer
        {
            const float* Asb = &As[buf][0][0];
            const float* Bsb = &Bs[buf][0][0];
            int mrow = warp * 16 + g;
            uint32_t a0 = __float_as_uint(Asb[t * SSTR + mrow]);
            uint32_t a1 = __float_as_uint(Asb[t * SSTR + mrow + 8]);
            uint32_t a2 = __float_as_uint(Asb[(t + 4) * SSTR + mrow]);
            uint32_t a3 = __float_as_uint(Asb[(t + 4) * SSTR + mrow + 8]);
#pragma unroll
            for (int j = 0; j < 16; j++) {
                uint32_t b0 = __float_as_uint(Bsb[t * SSTR + j * 8 + g]);
                uint32_t b1 = __float_as_uint(Bsb[(t + 4) * SSTR + j * 8 + g]);
                mma_tf32(acc[j], a0, a1, a2, a3, b0, b1);
            }
        }
        buf ^= 1;
        As[buf][aq + 0][am] = __uint_as_float(f2tf32(a4.x));
        As[buf][aq + 1][am] = __uint_as_float(f2tf32(a4.y));
        As[buf][aq + 2][am] = __uint_as_float(f2tf32(a4.z));
        As[buf][aq + 3][am] = __uint_as_float(f2tf32(a4.w));
        float4 bc;
        bc.x = __uint_as_float(f2tf32(b4.x));
        bc.y = __uint_as_float(f2tf32(b4.y));
        bc.z = __uint_as_float(f2tf32(b4.z));
        bc.w = __uint_as_float(f2tf32(b4.w));
        *(float4*)&Bs[buf][bk][bn] = bc;
        __syncthreads();
    }

    // final buffer compute
    {
        const float* Asb = &As[buf][0][0];
        const float* Bsb = &Bs[buf][0][0];
        int mrow = warp * 16 + g;
        uint32_t a0 = __float_as_uint(Asb[t * SSTR + mrow]);
        uint32_t a1 = __float_as_uint(Asb[t * SSTR + mrow + 8]);
        uint32_t a2 = __float_as_uint(Asb[(t + 4) * SSTR + mrow]);
        uint32_t a3 = __float_as_uint(Asb[(t + 4) * SSTR + mrow + 8]);
#pragma unroll
        for (int j = 0; j < 16; j++) {
            uint32_t b0 = __float_as_uint(Bsb[t * SSTR + j * 8 + g]);
            uint32_t b1 = __float_as_uint(Bsb[(t + 4) * SSTR + j * 8 + g]);
            mma_tf32(acc[j], a0, a1, a2, a3, b0, b1);
        }
    }

    // ---- epilogue: rows r0 = m0 + warp*16 + g and r0+8; cols n0 + j*8 + 2t, +1 ----
    int r0 = m0 + warp * 16 + g;
    float s1a = 0.f, s2a = 0.f, s1b = 0.f, s2b = 0.f;
#pragma unroll
    for (int j = 0; j < 16; j++) {
        int c = n0 + j * 8 + 2 * t;
        float2 bb = *(const float2*)(bias + c);
        float v00 = acc[j][0] + bb.x;
        float v01 = acc[j][1] + bb.y;
        float v10 = acc[j][2] + bb.x;
        float v11 = acc[j][3] + bb.y;
        if (ACT == 1) {
            float u;
            u = v00; v00 = 0.5f * u * (1.f + fast_tanh(0.7978845608028654f * (u + 0.044715f * u * u * u)));
            u = v01; v01 = 0.5f * u * (1.f + fast_tanh(0.7978845608028654f * (u + 0.044715f * u * u * u)));
            u = v10; v10 = 0.5f * u * (1.f + fast_tanh(0.7978845608028654f * (u + 0.044715f * u * u * u)));
            u = v11; v11 = 0.5f * u * (1.f + fast_tanh(0.7978845608028654f * (u + 0.044715f * u * u * u)));
        }
        if (RES == 1) {
            float2 ra = *(const float2*)(Cres + (size_t)r0 * Nc + c);
            float2 rb = *(const float2*)(Cres + (size_t)(r0 + 8) * Nc + c);
            v00 += ra.x; v01 += ra.y; v10 += rb.x; v11 += rb.y;
        }
        float2 oa; oa.x = v00; oa.y = v01;
        float2 ob; ob.x = v10; ob.y = v11;
        *(float2*)(C + (size_t)r0 * Nc + c) = oa;
        *(float2*)(C + (size_t)(r0 + 8) * Nc + c) = ob;
        if (STATS) {
            s1a += v00 + v01; s2a += v00 * v00 + v01 * v01;
            s1b += v10 + v11; s2b += v10 * v10 + v11 * v11;
        }
    }
    if (STATS) {
        // each row is fully owned by the 4 lanes of this quad (same g)
#pragma unroll
        for (int off = 1; off < 4; off <<= 1) {
            s1a += __shfl_xor_sync(0xffffffffu, s1a, off);
            s2a += __shfl_xor_sync(0xffffffffu, s2a, off);
            s1b += __shfl_xor_sync(0xffffffffu, s1b, off);
            s2b += __shfl_xor_sync(0xffffffffu, s2b, off);
        }
        if (t == 0) {
            float mean = s1a * (1.f / 128.f);
            float var  = s2a * (1.f / 128.f) - mean * mean;
            g_mu[r0]  = mean;
            g_rsd[r0] = rsqrtf(var + 1e-5f);
            mean = s1b * (1.f / 128.f);
            var  = s2b * (1.f / 128.f) - mean * mean;
            g_mu[r0 + 8]  = mean;
            g_rsd[r0 + 8] = rsqrtf(var + 1e-5f);
        }
    }
}

// ---------------- ragged attention: one CTA per (graph, head), 12 warps ----------------
#define ATTN_WARPS 12
#define ATTN_SMEM ((2 * LCAP * 33) * (int)sizeof(float) + ATTN_WARPS * LCAP * (int)sizeof(float4))

__global__ void __launch_bounds__(32 * ATTN_WARPS, 2) attn_kernel(const float* __restrict__ qkv,
                                                                  float* __restrict__ yout) {
    extern __shared__ float sm[];
    float*  Ks  = sm;
    float*  Vs  = sm + LCAP * 33;
    float4* Pr4 = (float4*)(sm + 2 * LCAP * 33);
    int g = blockIdx.x, h = blockIdx.y;
    int base = g_off[g];
    int L = g_off[g + 1] - base;
    if (L <= 0) return;
    if (L > LCAP) L = LCAP;
    int tid = threadIdx.x;

    int Lpad = (L + 127) & ~127;
    if (Lpad > LCAP) Lpad = LCAP;
    for (int idx = tid; idx < Lpad * 32; idx += 32 * ATTN_WARPS) {
        int m = idx >> 5, d = idx & 31;
        float kv = 0.f, vv = 0.f;
        if (m < L) {
            const float* p = qkv + (size_t)(base + m) * 384 + h * 32 + d;
            kv = p[128];
            vv = p[256];
        }
        Ks[m * 33 + d] = kv;
        Vs[m * 33 + d] = vv;
    }
    __syncthreads();

    int warp = tid >> 5, lane = tid & 31;
    float4* prw = Pr4 + warp * LCAP;
    const float scale = 0.17677669529663687f;
    int ngrp = (L + 3) >> 2;
    int njt = (L + 31) >> 5;

    for (int grp = warp; grp < ngrp; grp += ATTN_WARPS) {
        int q0 = grp * 4;
        float qreg[4];
#pragma unroll
        for (int qi = 0; qi < 4; qi++) {
            int q = q0 + qi;
            qreg[qi] = (q < L) ? qkv[(size_t)(base + q) * 384 + h * 32 + lane] : 0.f;
        }
        float s[4][7];
#pragma unroll
        for (int qi = 0; qi < 4; qi++)
#pragma unroll
            for (int j = 0; j < 7; j++) s[qi][j] = 0.f;

        for (int d = 0; d < 32; d++) {
            float kd[7];
#pragma unroll
            for (int j = 0; j < 7; j++) kd[j] = (j < njt) ? Ks[(lane + 32 * j) * 33 + d] : 0.f;
#pragma unroll
            for (int qi = 0; qi < 4; qi++) {
                float qd = __shfl_sync(0xffffffffu, qreg[qi], d);
#pragma unroll
                for (int j = 0; j < 7; j++) s[qi][j] += qd * kd[j];
            }
        }

#pragma unroll
        for (int qi = 0; qi < 4; qi++) {
            float mx = -3e38f;
#pragma unroll
            for (int j = 0; j < 7; j++) {
                int m = lane + 32 * j;
                s[qi][j] = (m < L) ? s[qi][j] * scale : -3e38f;
                mx = fmaxf(mx, s[qi][j]);
            }
            for (int off = 16; off; off >>= 1) mx = fmaxf(mx, __shfl_xor_sync(0xffffffffu, mx, off));
            float sum = 0.f;
#pragma unroll
            for (int j = 0; j < 7; j++) { float e = __expf(s[qi][j] - mx); s[qi][j] = e; sum += e; }
            for (int off = 16; off; off >>= 1) sum += __shfl_xor_sync(0xffffffffu, sum, off);
            float inv = 1.f / sum;
#pragma unroll
            for (int j = 0; j < 7; j++) s[qi][j] *= inv;
        }
#pragma unroll
        for (int j = 0; j < 7; j++) {
            if (j < njt) {
                float4 p; p.x = s[0][j]; p.y = s[1][j]; p.z = s[2][j]; p.w = s[3][j];
                prw[lane + 32 * j] = p;
            }
        }
        __syncwarp();

        float o[4] = {0.f, 0.f, 0.f, 0.f};
        for (int m = 0; m < L; m++) {
            float4 p = prw[m];
            float v = Vs[m * 33 + lane];
            o[0] += p.x * v; o[1] += p.y * v; o[2] += p.z * v; o[3] += p.w * v;
        }
#pragma unroll
        for (int qi = 0; qi < 4; qi++) {
            int q = q0 + qi;
            if (q < L) yout[(size_t)(base + q) * 128 + h * 32 + lane] = o[qi];
        }
        __syncwarp();
    }
}

// ---------------- final LN (stats precomputed) + 128 -> 4 proj + sigmoid ----------------
__global__ void out_proj(const float* __restrict__ x,
                         const float* __restrict__ lng, const float* __restrict__ lnb,
                         const float* __restrict__ w,
                         const float* __restrict__ b, float* __restrict__ out) {
    int t = blockIdx.x * 8 + (threadIdx.x >> 5);
    int lane = threadIdx.x & 31;
    float4 v = ((const float4*)(x + (size_t)t * 128))[lane];
    float mean = g_mu[t];
    float rs   = g_rsd[t];
    float4 g4 = ((const float4*)lng)[lane];
    float4 b4 = ((const float4*)lnb)[lane];
    float vv[4];
    vv[0] = (v.x - mean) * rs * g4.x + b4.x;
    vv[1] = (v.y - mean) * rs * g4.y + b4.y;
    vv[2] = (v.z - mean) * rs * g4.z + b4.z;
    vv[3] = (v.w - mean) * rs * g4.w + b4.w;

    float a[4] = {0.f, 0.f, 0.f, 0.f};
    const float* wr = w + lane * 16;
#pragma unroll
    for (int r = 0; r < 4; r++)
#pragma unroll
        for (int o = 0; o < 4; o++) a[o] += vv[r] * wr[r * 4 + o];
    for (int off = 16; off; off >>= 1)
#pragma unroll
        for (int o = 0; o < 4; o++) a[o] += __shfl_xor_sync(0xffffffffu, a[o], off);
    if (lane == 0) {
        out[t * 4 + 0] = a[0] + b[0];
        out[t * 4 + 1] = a[1] + b[1];
        out[t * 4 + 2] = a[2] + b[2];
        float z = a[3] + b[3];
        out[t * 4 + 3] = 1.f / (1.f + expf(-z));
    }
}

// ---------------- launch ----------------
extern "C" void kernel_launch(void* const* d_in, const int* in_sizes, int n_in,
                              void* d_out, int out_size) {
    (void)in_sizes; (void)n_in; (void)out_size;
    const float* s13  = (const float*)d_in[0];
    const float* v3   = (const float*)d_in[1];
    const int*   bidx = (const int*)d_in[2];
    const float* bn_g = (const float*)d_in[3];
    const float* bn_b = (const float*)d_in[4];
    const float* w_in = (const float*)d_in[5];
    const float* b_in = (const float*)d_in[6];
    const float* ln1g = (const float*)d_in[7];
    const float* ln1b = (const float*)d_in[8];
    const float* wqkv = (const float*)d_in[9];
    const float* bqkv = (const float*)d_in[10];
    const float* wo   = (const float*)d_in[11];
    const float* bo   = (const float*)d_in[12];
    const float* ln2g = (const float*)d_in[13];
    const float* ln2b = (const float*)d_in[14];
    const float* wm1  = (const float*)d_in[15];
    const float* bm1  = (const float*)d_in[16];
    const float* wm2  = (const float*)d_in[17];
    const float* bm2  = (const float*)d_in[18];
    const float* lnfg = (const float*)d_in[19];
    const float* lnfb = (const float*)d_in[20];
    const float* wout = (const float*)d_in[21];
    const float* bout = (const float*)d_in[22];

    float *x, *y, *qkv, *h1;
    cudaGetSymbolAddress((void**)&x,   g_x);
    cudaGetSymbolAddress((void**)&y,   g_y);
    cudaGetSymbolAddress((void**)&qkv, g_qkv);
    cudaGetSymbolAddress((void**)&h1,  g_h1);

    cudaFuncSetAttribute(attn_kernel, cudaFuncAttributeMaxDynamicSharedMemorySize, ATTN_SMEM);

    offsets_kernel<<<1, 192>>>(bidx);
    bn_stats<<<16, 256>>>(s13, v3);
    input_proj<<<NTOK, 128>>>(s13, v3, bn_g, bn_b, w_in, b_in, x);   // writes x + ln1 stats

    for (int i = 0; i < NBLK; i++) {
        // qkv = LN1(x) @ wqkv + b
        gemm_tc<0, 0, 1, 0><<<dim3(128, 3), 256>>>(x, wqkv + (size_t)i * 128 * 384, bqkv + i * 384,
                                                   x, qkv, 128, 384, ln1g + i * 128, ln1b + i * 128);
        attn_kernel<<<dim3(NGRAPH, 4), 32 * ATTN_WARPS, ATTN_SMEM>>>(qkv, y);
        // x += y @ wo + b ; epilogue writes LN2 stats
        gemm_tc<0, 1, 0, 1><<<dim3(128, 1), 256>>>(y, wo + (size_t)i * 128 * 128, bo + i * 128,
                                                   x, x, 128, 128, ln1g, ln1b);
        // h1 = gelu(LN2(x) @ wm1 + b)
        gemm_tc<1, 0, 1, 0><<<dim3(128, 4), 256>>>(x, wm1 + (size_t)i * 128 * 512, bm1 + i * 512,
                                                   x, h1, 128, 512, ln2g + i * 128, ln2b + i * 128);
        // x += h1 @ wm2 + b ; epilogue writes stats for next ln1 / final LN
        gemm_tc<0, 1, 0, 1><<<dim3(128, 1), 256>>>(h1, wm2 + (size_t)i * 512 * 128, bm2 + i * 128,
                                                   x, x, 512, 128, ln2g, ln2b);
    }

    out_proj<<<NTOK / 8, 256>>>(x, lnfg, lnfb, wout, bout, (float*)d_out);
}